// round 17
// baseline (speedup 1.0000x reference)
#include <cuda_runtime.h>
#include <math.h>

#define GN 256
#define NVOX (GN*GN*GN)          // 2^24
#define MAX_ID 32
#define NUM_CLASSES 13
#define NBINS ((MAX_ID+1)*NUM_CLASSES)   // 429
#define LUT_SZ (MAX_ID+3)                // 35
#define KEY_WALL  33
#define KEY_FLOOR 34
#define SURF_BIT  0x80
#define NCOPY 16

// ---------------- device scratch (no allocations allowed) ----------------
__device__ int           g_counts[NBINS];
__device__ int           g_sem_lut[LUT_SZ];
__device__ unsigned char g_labellut[256];  // key byte -> label | (key&0x80)
__device__ unsigned char g_key[NVOX];      // bit7=surface, low: 33=wall,34=floor,else inst
__device__ unsigned char g_lab[NVOX];      // bit7=surface, low7: panoptic label
__device__ unsigned char g_W1[NVOX];       // first positive label in k-window [k-3,k+2]
__device__ unsigned char g_W2[NVOX];       // first positive over (dj,dk) window

__device__ const float* g_geo;
__device__ const int*   g_inst;
__device__ const int*   g_sem;

// per-byte "full mask where byte nonzero" (bytes must be <= 0x7F)
__device__ __forceinline__ unsigned long long nzmask(unsigned long long r) {
    unsigned long long m = (r + 0x7F7F7F7F7F7F7F7FULL) & 0x8080808080808080ULL;
    return m | (m - (m >> 7));
}
// fold: keep r's byte where nonzero, else take s's byte
__device__ __forceinline__ void fold(unsigned long long& r, unsigned long long s) {
    r |= s & ~nzmask(r);
}

// ---------------- kernel A: classify big buffers by content (3 warps) ----------------
__global__ void classifyK(const int* a, const int* b, const int* c) {
    __shared__ int smax[3];
    const int* bufs[3] = { a, b, c };
    int w = threadIdx.x >> 5, lane = threadIdx.x & 31;
    if (w < 3) {
        const int* p = bufs[w];
        int mx = -2147483647;
        for (int i = lane; i < 2048; i += 32) {
            int v = p[i * 769];
            mx = v > mx ? v : mx;
        }
        for (int o = 16; o > 0; o >>= 1) {
            int t = __shfl_xor_sync(0xFFFFFFFFu, mx, o);
            mx = t > mx ? t : mx;
        }
        if (lane == 0) smax[w] = mx;
    }
    __syncthreads();
    if (threadIdx.x == 0) {
        bool used[3] = { false, false, false };
        bool gs = false, ss = false, is = false;
        for (int t = 0; t < 3; t++)
            if (!used[t] && (smax[t] > 1000000 || smax[t] < 0)) {
                g_geo = (const float*)bufs[t]; used[t] = true; gs = true; break;
            }
        for (int t = 0; t < 3; t++)
            if (!used[t] && smax[t] < 13) {
                g_sem = bufs[t]; used[t] = true; ss = true; break;
            }
        for (int t = 0; t < 3; t++)
            if (!used[t]) { g_inst = bufs[t]; used[t] = true; is = true; break; }
        if (!gs) g_geo  = (const float*)a;
        if (!ss) g_sem  = c;
        if (!is) g_inst = b;
    }
    for (int i = threadIdx.x; i < NBINS; i += blockDim.x) g_counts[i] = 0;
}

// ---------------- kernel 1: joint histogram (lane-private copies) + key grid ----------------
__global__ void histK() {
    __shared__ int sc[NBINS * NCOPY];
    for (int i = threadIdx.x; i < NBINS * NCOPY; i += blockDim.x) sc[i] = 0;
    __syncthreads();

    const int4*   inst4 = (const int4*)g_inst;
    const int4*   sem4  = (const int4*)g_sem;
    const float4* geo4  = (const float4*)g_geo;
    uchar4*       key4  = (uchar4*)g_key;
    int copy = threadIdx.x & (NCOPY - 1);
    int stride = gridDim.x * blockDim.x;
    int n4 = NVOX / 4;
    for (int i = blockIdx.x * blockDim.x + threadIdx.x; i < n4; i += stride) {
        int4   v = inst4[i];
        int4   s = sem4[i];
        float4 g = geo4[i];
        unsigned ix;
        ix = (unsigned)(v.x * NUM_CLASSES + s.x); if (ix < NBINS) atomicAdd(&sc[ix * NCOPY + copy], 1);
        ix = (unsigned)(v.y * NUM_CLASSES + s.y); if (ix < NBINS) atomicAdd(&sc[ix * NCOPY + copy], 1);
        ix = (unsigned)(v.z * NUM_CLASSES + s.z); if (ix < NBINS) atomicAdd(&sc[ix * NCOPY + copy], 1);
        ix = (unsigned)(v.w * NUM_CLASSES + s.w); if (ix < NBINS) atomicAdd(&sc[ix * NCOPY + copy], 1);
        uchar4 k;
        k.x = ((s.x == 10) ? KEY_WALL : ((s.x == 11) ? KEY_FLOOR : (unsigned char)(v.x & 31)))
            | (fabsf(g.x) <= 1.5f ? SURF_BIT : 0);
        k.y = ((s.y == 10) ? KEY_WALL : ((s.y == 11) ? KEY_FLOOR : (unsigned char)(v.y & 31)))
            | (fabsf(g.y) <= 1.5f ? SURF_BIT : 0);
        k.z = ((s.z == 10) ? KEY_WALL : ((s.z == 11) ? KEY_FLOOR : (unsigned char)(v.z & 31)))
            | (fabsf(g.z) <= 1.5f ? SURF_BIT : 0);
        k.w = ((s.w == 10) ? KEY_WALL : ((s.w == 11) ? KEY_FLOOR : (unsigned char)(v.w & 31)))
            | (fabsf(g.w) <= 1.5f ? SURF_BIT : 0);
        key4[i] = k;
    }
    __syncthreads();
    for (int bin = threadIdx.x; bin < NBINS; bin += blockDim.x) {
        int s = 0;
        #pragma unroll
        for (int c = 0; c < NCOPY; c++) s += sc[bin * NCOPY + c];
        if (s) atomicAdd(&g_counts[bin], s);
    }
}

// ---------------- kernel 2: build LUTs (parallelized over ids) ----------------
__global__ void lutK(const int* __restrict__ ids2d, int n2d) {
    __shared__ int  sh_hist[MAX_ID + 1];
    __shared__ int  sh_sel[MAX_ID + 1];
    __shared__ int  sh_pano[MAX_ID + 1];
    __shared__ bool sh_in2d[MAX_ID + 1];
    __shared__ bool sh_pres[MAX_ID + 1];
    int t = threadIdx.x;

    if (t <= MAX_ID) {
        int h = 0, bestv = -2147483647, bi = 0;
        for (int c = 0; c < NUM_CLASSES; c++) {
            int cnt = g_counts[t * NUM_CLASSES + c];
            h += cnt;
            int v = (c == 0 || c == 10 || c == 11) ? -1 : cnt;
            if (v > bestv) { bestv = v; bi = c; }   // first max wins
        }
        sh_hist[t] = h;
        sh_sel[t]  = bi;
        bool in2 = false;
        for (int s = 0; s < n2d; s++) {
            int v = ids2d[s] + 1;
            if (v == t && t >= 1) in2 = true;
        }
        sh_in2d[t] = in2;
    }
    __syncthreads();

    if (t == 0) {
        int zp = 0;
        for (int i = 0; i <= MAX_ID; i++)
            if (sh_hist[i] > 0 && !sh_in2d[i]) zp = 1;
        int rank = 0;
        sh_pano[0] = 0;
        sh_pres[0] = false;
        for (int i = 1; i <= MAX_ID; i++) {
            bool p = sh_in2d[i] && (sh_hist[i] > 0);
            sh_pres[i] = p;
            if (p) rank++;
            sh_pano[i] = p ? (rank - 1 + zp + 2) : 0;
        }
        for (int k = 0; k < LUT_SZ; k++) g_sem_lut[k] = 0;
        g_sem_lut[1] = 10;
        g_sem_lut[2] = 11;
        for (int i = 1; i <= MAX_ID; i++) {
            int idx = sh_pano[i];
            int val = sh_pres[i] ? sh_sel[i] : 0;
            if (idx >= 0 && idx < LUT_SZ) g_sem_lut[idx] = val;
        }
    }
    __syncthreads();

    for (int x = t; x < 256; x += blockDim.x) {
        int base = x & 0x7F;
        unsigned char val = 0;
        if (base < 32)             val = (unsigned char)sh_pano[base];
        else if (base == KEY_WALL)   val = 1;
        else if (base == KEY_FLOOR)  val = 2;
        g_labellut[x] = val | (unsigned char)(x & SURF_BIT);
    }
}

// ---------------- kernel 3: labelize + k-window W1 via byte-cascade ----------------
// 16 lanes per 256-byte row (lane&15 = segment); torus halo via shfl.
__global__ void labelK() {
    __shared__ unsigned char lut[256];
    if (threadIdx.x < 256) lut[threadIdx.x] = g_labellut[threadIdx.x];
    __syncthreads();

    int t = blockIdx.x * blockDim.x + threadIdx.x;
    int lane = threadIdx.x & 31;

    uint4 kin = ((const uint4*)g_key)[t];

    unsigned long long lb_lo = 0, lb_hi = 0, pl_lo = 0, pl_hi = 0;
    unsigned kw[4] = { kin.x, kin.y, kin.z, kin.w };
    #pragma unroll
    for (int wd = 0; wd < 4; wd++) {
        #pragma unroll
        for (int n = 0; n < 4; n++) {
            unsigned x = (kw[wd] >> (8 * n)) & 0xFF;
            unsigned long long c = lut[x];
            int bytep = wd * 4 + n;
            if (bytep < 8) { lb_lo |= c << (8 * bytep); pl_lo |= (c & 0x7F) << (8 * bytep); }
            else           { lb_hi |= c << (8 * (bytep - 8)); pl_hi |= (c & 0x7F) << (8 * (bytep - 8)); }
        }
    }

    int prevLane = (lane & 16) | ((lane - 1) & 15);
    int nextLane = (lane & 16) | ((lane + 1) & 15);
    unsigned prev3 = __shfl_sync(0xFFFFFFFFu, (unsigned)(pl_hi >> 40), prevLane); // bytes 13,14,15
    unsigned next2 = __shfl_sync(0xFFFFFFFFu, (unsigned)(pl_lo & 0xFFFF), nextLane); // bytes 0,1

    unsigned long long e0 = (unsigned long long)prev3 | (pl_lo << 24);        // e[0..7]
    unsigned long long e1 = (pl_lo >> 40) | (pl_hi << 24);                     // e[8..15]
    unsigned long long e2 = (pl_hi >> 40) | ((unsigned long long)next2 << 24); // e[16..20]

    // W1[b] = first nonzero of e[b..b+5] : cascade 6 shifted streams
    unsigned long long r_lo = e0, r_hi = e1;
    #pragma unroll
    for (int q = 1; q < 6; q++) {
        unsigned long long s_lo = (e0 >> (8 * q)) | (e1 << (64 - 8 * q));
        unsigned long long s_hi = (e1 >> (8 * q)) | (e2 << (64 - 8 * q));
        fold(r_lo, s_lo);
        fold(r_hi, s_hi);
    }

    uint4 lout, wout;
    lout.x = (unsigned)lb_lo; lout.y = (unsigned)(lb_lo >> 32);
    lout.z = (unsigned)lb_hi; lout.w = (unsigned)(lb_hi >> 32);
    wout.x = (unsigned)r_lo;  wout.y = (unsigned)(r_lo >> 32);
    wout.z = (unsigned)r_hi;  wout.w = (unsigned)(r_hi >> 32);
    ((uint4*)g_lab)[t] = lout;
    ((uint4*)g_W1)[t]  = wout;
}

// ---------------- kernel 4: W2 = first positive over dj of W1 (coalesced) ----------------
__global__ void w2K() {
    int t = blockIdx.x * blockDim.x + threadIdx.x;   // uint4 index
    int seg = t & 15;
    int j = (t >> 4) & 255;
    int ibase = (t >> 12) << 12;
    unsigned long long r_lo = 0, r_hi = 0;
    #pragma unroll
    for (int dj = -3; dj < 3; dj++) {
        int jj = (j + dj) & 255;
        uint4 w = ((const uint4*)g_W1)[ibase | (jj << 4) | seg];
        unsigned long long s_lo = (unsigned long long)w.x | ((unsigned long long)w.y << 32);
        unsigned long long s_hi = (unsigned long long)w.z | ((unsigned long long)w.w << 32);
        if (dj == -3) { r_lo = s_lo; r_hi = s_hi; }
        else          { fold(r_lo, s_lo); fold(r_hi, s_hi); }
    }
    uint4 o;
    o.x = (unsigned)r_lo; o.y = (unsigned)(r_lo >> 32);
    o.z = (unsigned)r_hi; o.w = (unsigned)(r_hi >> 32);
    ((uint4*)g_W2)[t] = o;
}

// ---------------- kernel 5: W3 over di + final outputs (branch-free) ----------------
__global__ void nnK(float* __restrict__ out, long long out_elems) {
    __shared__ float slut[LUT_SZ];
    if (threadIdx.x < LUT_SZ) slut[threadIdx.x] = (float)g_sem_lut[threadIdx.x];
    __syncthreads();

    int t = blockIdx.x * blockDim.x + threadIdx.x;   // uint4 index: 16 voxels
    int seg = t & 15;
    int jpart = t & 0xFF0;          // j<<4 bits
    int i = t >> 12;

    uint4 lv = ((const uint4*)g_lab)[t];
    unsigned long long lab_lo = (unsigned long long)lv.x | ((unsigned long long)lv.y << 32);
    unsigned long long lab_hi = (unsigned long long)lv.z | ((unsigned long long)lv.w << 32);

    unsigned long long r_lo = 0, r_hi = 0;
    #pragma unroll
    for (int di = -3; di < 3; di++) {
        int ii = (i + di) & 255;
        uint4 w = ((const uint4*)g_W2)[(ii << 12) | jpart | seg];
        unsigned long long s_lo = (unsigned long long)w.x | ((unsigned long long)w.y << 32);
        unsigned long long s_hi = (unsigned long long)w.z | ((unsigned long long)w.w << 32);
        if (di == -3) { r_lo = s_lo; r_hi = s_hi; }
        else          { fold(r_lo, s_lo); fold(r_hi, s_hi); }
    }

    float pano[16], semf[16];
    #pragma unroll
    for (int b = 0; b < 16; b++) {
        unsigned raw, w3;
        if (b < 8) { raw = (unsigned)(lab_lo >> (8 * b)) & 0xFF; w3 = (unsigned)(r_lo >> (8 * b)) & 0xFF; }
        else       { raw = (unsigned)(lab_hi >> (8 * (b - 8))) & 0xFF; w3 = (unsigned)(r_hi >> (8 * (b - 8))) & 0xFF; }
        int label = (raw == 0x80u) ? (int)w3 : (int)(raw & 0x7F);
        pano[b] = (float)label;
        semf[b] = slut[label];
    }

    long long vbase = (long long)t * 16;
    float4* po = (float4*)out + t * 4;
    float4* so = (float4*)(out + NVOX) + t * 4;
    #pragma unroll
    for (int h = 0; h < 4; h++) {
        if (vbase + h * 4 + 3 < out_elems)
            po[h] = make_float4(pano[h*4], pano[h*4+1], pano[h*4+2], pano[h*4+3]);
        if (vbase + (long long)NVOX + h * 4 + 3 < out_elems)
            so[h] = make_float4(semf[h*4], semf[h*4+1], semf[h*4+2], semf[h*4+3]);
    }
}

// ---------------- launch ----------------
extern "C" void kernel_launch(void* const* d_in, const int* in_sizes, int n_in,
                              void* d_out, int out_size) {
    const int* big[3] = { 0, 0, 0 };
    const int* ids2d = 0;
    int n2d = 0, nb = 0;
    for (int t = 0; t < n_in; t++) {
        if (in_sizes[t] < 1024) { ids2d = (const int*)d_in[t]; n2d = in_sizes[t]; }
        else if (nb < 3)        { big[nb++] = (const int*)d_in[t]; }
    }

    float* out = (float*)d_out;
    long long out_elems = (long long)out_size;

    classifyK<<<1, 128>>>(big[0], big[1], big[2]);
    histK<<<2048, 256>>>();
    if (ids2d) lutK<<<1, 64>>>(ids2d, n2d);
    labelK<<<NVOX / 16 / 256, 256>>>();
    w2K<<<NVOX / 16 / 256, 256>>>();
    nnK<<<NVOX / 16 / 256, 256>>>(out, out_elems);
}